// round 14
// baseline (speedup 1.0000x reference)
#include <cuda_runtime.h>

#define EPS 1e-7f
#define NDIM 64
#define TBINS 32
#define NKEY (NDIM * TBINS)          // 2048 sort keys
#define MAXN 32768
#define MAXR 2048
#define MAXCHUNKS 128
#define NSLAB 4   // strided slabs per (r-block, dim) -> balanced work, 1 wave
#define DWS 0.35f // Ks window half-width
#define DWC 0.15f // Kc window half-width
#define LOG2E 1.4426950408889634f
#define VSCALE 8388608.0f
#define VSCALE_INV 1.1920928955078125e-7f

typedef unsigned long long ull;

// ---------------- device scratch ----------------
__device__ ulonglong2 g_bc[MAXN];               // {B,B},{C,C} per point, (d,tbin)-sorted
__device__ ull    g_vv[MAXN];                   // {v,v}
__device__ int    g_binoff[NKEY + 1];           // global offset per key
__device__ unsigned short g_chunkhist[MAXCHUNKS][NKEY]; // [chunk][key]
__device__ unsigned short g_chunkcum [MAXCHUNKS][NKEY]; // exclusive chunk prefix per key
__device__ ull    g_chunkvsum[MAXCHUNKS][NDIM];
__device__ float  g_sumv[NDIM];
__device__ float4 g_acc[MAXR * NSLAB * NDIM];   // [r][z][d] = {ws, wsv, wc, wcv}

// ---------------- f32x2 packed helpers (sm_100a) ----------------
__device__ __forceinline__ ull pack2(float lo, float hi) {
    ull r; asm("mov.b64 %0, {%1, %2};" : "=l"(r) : "f"(lo), "f"(hi)); return r;
}
__device__ __forceinline__ void unpack2(ull p, float& lo, float& hi) {
    asm("mov.b64 {%0, %1}, %2;" : "=f"(lo), "=f"(hi) : "l"(p));
}
__device__ __forceinline__ ull add2(ull a, ull b) {
    ull r; asm("add.rn.f32x2 %0, %1, %2;" : "=l"(r) : "l"(a), "l"(b)); return r;
}
__device__ __forceinline__ ull mul2(ull a, ull b) {
    ull r; asm("mul.rn.f32x2 %0, %1, %2;" : "=l"(r) : "l"(a), "l"(b)); return r;
}
__device__ __forceinline__ ull fma2(ull a, ull b, ull c) {
    ull r; asm("fma.rn.f32x2 %0, %1, %2, %3;" : "=l"(r) : "l"(a), "l"(b), "l"(c)); return r;
}
__device__ __forceinline__ float ex2f(float x) {
    float y; asm("ex2.approx.f32 %0, %1;" : "=f"(y) : "f"(x)); return y;
}

// ---------------- P1: per-chunk 2048-key histogram + per-dim v sums ----------------
__global__ void k_hist(const float* __restrict__ S, int n) {
    __shared__ int h[NKEY];
    __shared__ ull vs[NDIM];
    const int tid = threadIdx.x;
    for (int j = tid; j < NKEY; j += 256) h[j] = 0;
    if (tid < NDIM) vs[tid] = 0ULL;
    __syncthreads();
    int i = blockIdx.x * 256 + tid;
    if (i < n) {
        float t = S[i * 3 + 0];
        float v = S[i * 3 + 1];
        int d = (int)S[i * 3 + 2];
        int tb = (int)(t * (float)TBINS);
        tb = max(0, min(TBINS - 1, tb));
        atomicAdd(&h[d * TBINS + tb], 1);
        atomicAdd(&vs[d], (ull)(long long)llrintf(v * VSCALE));
    }
    __syncthreads();
    for (int j = tid; j < NKEY; j += 256)
        g_chunkhist[blockIdx.x][j] = (unsigned short)h[j];
    if (tid < NDIM) g_chunkvsum[blockIdx.x][tid] = vs[tid];
}

// ---------------- P2: fused scan (1 block x 1024 thr; thread owns keys tid, tid+1024) --
__global__ void k_scan(int nchunks) {
    __shared__ int sA[1024], sB[1024];
    __shared__ ull vred[1024];
    const int tid = threadIdx.x;
    const int kA = tid, kB = tid + 1024;

    int runA = 0, runB = 0;
    for (int c = 0; c < nchunks; c++) {           // coalesced across threads
        int xA = g_chunkhist[c][kA];
        int xB = g_chunkhist[c][kB];
        g_chunkcum[c][kA] = (unsigned short)runA;
        g_chunkcum[c][kB] = (unsigned short)runB;
        runA += xA; runB += xB;
    }

    // per-dim v sums: thread (d = tid>>4, q = tid&15)
    {
        const int d = tid >> 4, q = tid & 15;
        ull acc = 0ULL;
        for (int c = q; c < nchunks; c += 16) acc += g_chunkvsum[c][d];
        vred[tid] = acc;
    }
    __syncthreads();
    if ((tid & 15) == 0) {
        ull a = 0ULL;
        for (int j = 0; j < 16; j++) a += vred[tid + j];
        g_sumv[tid >> 4] = (float)((long long)a) * VSCALE_INV;
    }

    // dual Hillis-Steele inclusive scans over 1024 key-totals each
    int incA = runA, incB = runB;
    sA[tid] = incA; sB[tid] = incB;
    __syncthreads();
    for (int ofs = 1; ofs < 1024; ofs <<= 1) {
        int aA = 0, aB = 0;
        if (tid >= ofs) { aA = sA[tid - ofs]; aB = sB[tid - ofs]; }
        __syncthreads();
        incA += aA; incB += aB;
        sA[tid] = incA; sB[tid] = incB;
        __syncthreads();
    }
    const int totalA = sA[1023];
    g_binoff[kA] = incA - runA;                   // exclusive prefix
    g_binoff[kB] = totalA + incB - runB;
    if (tid == 1023) g_binoff[NKEY] = totalA + incB;
}

// ---------------- P3: stable scatter, two-phase parallel rank (2 syncs) -------------
__global__ void k_scatter(const float* __restrict__ S,
                          const float* __restrict__ alpha,
                          int n) {
    __shared__ unsigned char wcnt[8][NKEY];       // per-warp per-key counts (16KB)
    const int tid  = threadIdx.x;
    const int c    = blockIdx.x;
    const int lane = tid & 31;
    const int warp = tid >> 5;

    {
        unsigned int* w32 = (unsigned int*)&wcnt[0][0];
        for (int j = tid; j < (8 * NKEY) / 4; j += 256) w32[j] = 0u;
    }

    int i = c * 256 + tid;
    int key = -1;
    float t = 0.f, v = 0.f;
    if (i < n) {
        t = S[i * 3 + 0];
        v = S[i * 3 + 1];
        int d = (int)S[i * 3 + 2];
        int tb = (int)(t * (float)TBINS);
        tb = max(0, min(TBINS - 1, tb));
        key = d * TBINS + tb;
    }
    __syncthreads();

    // intra-warp stable rank among equal keys
    unsigned m  = __match_any_sync(0xffffffffu, key);
    int rw      = __popc(m & ((1u << lane) - 1));
    int ldr     = __ffs(m) - 1;

    // phase 1: leaders publish per-warp counts
    if (key >= 0 && lane == ldr) wcnt[warp][key] = (unsigned char)__popc(m);
    __syncthreads();

    if (key >= 0) {
        // phase 2: base = counts of earlier warps for this key
        int grpbase = 0;
#pragma unroll
        for (int w = 0; w < 8; w++)
            if (w < warp) grpbase += (int)wcnt[w][key];

        int pos = g_binoff[key] + (int)g_chunkcum[c][key] + grpbase + rw;
        float tm = (t > 0.0f) ? t : 1.0e9f;     // masked -> exp underflows to 0
        float negC = -__ldg(alpha) * LOG2E;
        float B = -2.0f * negC * tm;            // arg = A + B*r + C = negC*(r-t)^2
        float Cc = negC * tm * tm;
        ulonglong2 bc;
        bc.x = pack2(B, B);
        bc.y = pack2(Cc, Cc);
        g_bc[pos] = bc;
        g_vv[pos] = pack2(v, v);
    }
}

// ---------------- main: 128-thr CTAs, 2 r's/thread, strided slabs, 3-segment loop ---
// grid = (R/256=8, NDIM, NSLAB=4) = 2048 CTAs x 128 thr -> ~55 warps/SM, 1 wave
#define KS_LOOP(LIMIT, DO_KC)                                           \
    _Pragma("unroll 2")                                                 \
    for (; i < (LIMIT); i += NSLAB) {                                   \
        ulonglong2 bc = __ldg(&g_bc[i]);                                \
        ull vp = __ldg(&g_vv[i]);                                       \
        ull g = fma2(bc.x, rr, add2(bc.y, A));                          \
        float x0, x1;                                                   \
        unpack2(g, x0, x1);                                             \
        ull e = pack2(ex2f(x0), ex2f(x1));                              \
        ws  = add2(ws, e);                                              \
        wsv = fma2(e, vp, wsv);                                         \
        if (DO_KC) {                                                    \
            ull t2 = mul2(e, e), t4 = mul2(t2, t2);                     \
            ull e10 = mul2(mul2(t4, t4), t2);                           \
            wc  = add2(wc, e10);                                        \
            wcv = fma2(e10, vp, wcv);                                   \
        }                                                               \
    }

__global__ void __launch_bounds__(128) k_main(const float* __restrict__ ref,
                                              const float* __restrict__ alpha,
                                              int R) {
    const int d   = blockIdx.y;
    const int z   = blockIdx.z;
    const int tid = threadIdx.x;
    const int rb  = blockIdx.x * 256;

    const int r0 = rb + tid, r1 = r0 + 128;
    const int idx0 = (r0 * NSLAB + z) * NDIM + d;
    const int idx1 = (r1 * NSLAB + z) * NDIM + d;

    const float rlo = __ldg(ref + rb);
    const float rhi = __ldg(ref + rb + 255);

    // Ks window bins
    int sb0 = max(0, (int)floorf((rlo - DWS) * (float)TBINS));
    int sb1 = min(TBINS, (int)floorf((rhi + DWS) * (float)TBINS) + 1);
    const int s0 = g_binoff[d * TBINS + sb0];
    const int s1 = g_binoff[d * TBINS + sb1];

    // Kc window bins (nested: c0 >= s0, c1 <= s1)
    int cb0 = max(0, (int)floorf((rlo - DWC) * (float)TBINS));
    int cb1 = min(TBINS, (int)floorf((rhi + DWC) * (float)TBINS) + 1);
    const int c0 = g_binoff[d * TBINS + cb0];
    const int c1 = g_binoff[d * TBINS + cb1];

    const float negC = -__ldg(alpha) * LOG2E;
    const float f0 = __ldg(ref + r0), f1 = __ldg(ref + r1);
    const ull rr = pack2(f0, f1);
    const ull A  = pack2(negC * f0 * f0, negC * f1 * f1);

    ull ws = 0, wsv = 0, wc = 0, wcv = 0;

    // strided over slab z: i = s0+z, s0+z+NSLAB, ... ; segments carry i forward
    int i = s0 + z;
    KS_LOOP(c0, false)    // [s0+z, c0): Ks only
    KS_LOOP(c1, true)     // [.., c1):   Ks + Kc
    KS_LOOP(s1, false)    // [.., s1):   Ks only

    float a0, a1, b0, b1, u0, u1, w0, w1;
    unpack2(ws, a0, a1); unpack2(wsv, b0, b1);
    unpack2(wc, u0, u1); unpack2(wcv, w0, w1);
    g_acc[idx0] = make_float4(a0, b0, u0, w0);
    g_acc[idx1] = make_float4(a1, b1, u1, w1);
}

// ---------------- finalize: 512 blocks x 256 thr, 4 r's per block, float4 loads -----
__global__ void __launch_bounds__(256) k_finalize(const float* __restrict__ rho,
                                                  float* __restrict__ out,
                                                  int R, float Rinv) {
    __shared__ float s_lam[4][NDIM + 1];
    __shared__ float s_ksv[4][NDIM + 1];
    __shared__ float s_coa[4][NDIM + 1];
    __shared__ float s_den[4];

    const int tid = threadIdx.x;
    const int r0  = blockIdx.x * 4;
    const int d   = tid & 63;
    const int rl  = tid >> 6;
    const int r   = r0 + rl;

    {
        const int cnt = g_binoff[(d + 1) * TBINS] - g_binoff[d * TBINS];
        const float ec = EPS * (float)(cnt + 1);
        const float ev = EPS * g_sumv[d];
        float lam_s = ec, ksv = ev, lam_c = ec, kcv = ev;
#pragma unroll
        for (int z = 0; z < NSLAB; z++) {
            float4 a = g_acc[(r * NSLAB + z) * NDIM + d];   // coalesced
            lam_s += a.x; ksv += a.y; lam_c += a.z; kcv += a.w;
        }
        s_lam[rl][d] = lam_s;
        s_ksv[rl][d] = ksv;
        s_coa[rl][d] = __fdividef(kcv, lam_c);
    }
    __syncthreads();

    {
        const int wid  = tid >> 5;
        const int lane = tid & 31;
        if (wid < 4) {
            float p = s_lam[wid][lane] + s_lam[wid][lane + 32];
            p += __shfl_xor_sync(0xffffffffu, p, 16);
            p += __shfl_xor_sync(0xffffffffu, p, 8);
            p += __shfl_xor_sync(0xffffffffu, p, 4);
            p += __shfl_xor_sync(0xffffffffu, p, 2);
            p += __shfl_xor_sync(0xffffffffu, p, 1);
            if (lane == 0) s_den[wid] = p;
        }
    }
    __syncthreads();

    float acc = 0.0f;
#pragma unroll
    for (int k = 0; k < NDIM; k++)
        acc = fmaf(s_ksv[rl][k], __ldg(&rho[k * NDIM + d]), acc);
    const float cr = __fdividef(acc, s_den[rl]);

    float* o = out + (long long)r * (3 * NDIM);
    o[d]            = s_lam[rl][d] * Rinv;   // lam
    o[NDIM + d]     = cr;                    // cross
    o[2 * NDIM + d] = s_coa[rl][d] - cr;     // transient
}

// ---------------- launch ----------------
extern "C" void kernel_launch(void* const* d_in, const int* in_sizes, int n_in,
                              void* d_out, int out_size) {
    const float* S     = (const float*)d_in[0];
    const float* ref   = (const float*)d_in[1];
    const float* alpha = (const float*)d_in[2];
    const float* rho   = (const float*)d_in[3];
    const int n = in_sizes[0] / 3;
    const int R = in_sizes[1];
    int nchunks = (n + 255) / 256;
    if (nchunks > MAXCHUNKS) nchunks = MAXCHUNKS;

    k_hist<<<nchunks, 256>>>(S, n);
    k_scan<<<1, 1024>>>(nchunks);
    k_scatter<<<nchunks, 256>>>(S, alpha, n);

    dim3 gm(R / 256, NDIM, NSLAB);
    k_main<<<gm, 128>>>(ref, alpha, R);

    k_finalize<<<R / 4, 256>>>(rho, (float*)d_out, R, 1.0f / (float)R);
}

// round 16
// speedup vs baseline: 1.2983x; 1.2983x over previous
#include <cuda_runtime.h>

#define EPS 1e-7f
#define NDIM 64
#define TBINS 32
#define NKEY (NDIM * TBINS)          // 2048 sort keys
#define MAXN 32768
#define MAXR 2048
#define CHUNK 512
#define MAXCHUNKS 64
#define NSLAB 10  // strided slabs per (r-block, dim): 5120 CTAs -> refillable waves
#define DWS 0.32f // Ks window half-width: rel err ~1e-4 (calibrated)
#define DWC 0.15f // Kc window half-width: tail rel err ~2e-6
#define LOG2E 1.4426950408889634f
#define VSCALE 8388608.0f
#define VSCALE_INV 1.1920928955078125e-7f

typedef unsigned long long ull;

// ---------------- device scratch ----------------
__device__ ulonglong2 g_bc[MAXN];               // {B,B},{C,C} per point, (d,tbin)-sorted
__device__ ull    g_vv[MAXN];                   // {v,v}
__device__ int    g_binoff[NKEY + 1];           // global offset per key
__device__ unsigned short g_chunkhist[MAXCHUNKS][NKEY]; // [chunk][key]
__device__ unsigned short g_chunkcum [MAXCHUNKS][NKEY]; // exclusive chunk prefix per key
__device__ ull    g_chunkvsum[MAXCHUNKS][NDIM];
__device__ float  g_sumv[NDIM];
__device__ float4 g_acc[MAXR * NSLAB * NDIM];   // [r][z][d] = {ws, wsv, wc, wcv}

// ---------------- f32x2 packed helpers (sm_100a) ----------------
__device__ __forceinline__ ull pack2(float lo, float hi) {
    ull r; asm("mov.b64 %0, {%1, %2};" : "=l"(r) : "f"(lo), "f"(hi)); return r;
}
__device__ __forceinline__ void unpack2(ull p, float& lo, float& hi) {
    asm("mov.b64 {%0, %1}, %2;" : "=f"(lo), "=f"(hi) : "l"(p));
}
__device__ __forceinline__ ull add2(ull a, ull b) {
    ull r; asm("add.rn.f32x2 %0, %1, %2;" : "=l"(r) : "l"(a), "l"(b)); return r;
}
__device__ __forceinline__ ull mul2(ull a, ull b) {
    ull r; asm("mul.rn.f32x2 %0, %1, %2;" : "=l"(r) : "l"(a), "l"(b)); return r;
}
__device__ __forceinline__ ull fma2(ull a, ull b, ull c) {
    ull r; asm("fma.rn.f32x2 %0, %1, %2, %3;" : "=l"(r) : "l"(a), "l"(b), "l"(c)); return r;
}
__device__ __forceinline__ float ex2f(float x) {
    float y; asm("ex2.approx.f32 %0, %1;" : "=f"(y) : "f"(x)); return y;
}

// ---------------- P1: per-chunk 2048-key histogram + per-dim v sums (512 thr) -------
__global__ void k_hist(const float* __restrict__ S, int n) {
    __shared__ int h[NKEY];
    __shared__ ull vs[NDIM];
    const int tid = threadIdx.x;
    for (int j = tid; j < NKEY; j += CHUNK) h[j] = 0;
    if (tid < NDIM) vs[tid] = 0ULL;
    __syncthreads();
    int i = blockIdx.x * CHUNK + tid;
    if (i < n) {
        float t = S[i * 3 + 0];
        float v = S[i * 3 + 1];
        int d = (int)S[i * 3 + 2];
        int tb = (int)(t * (float)TBINS);
        tb = max(0, min(TBINS - 1, tb));
        atomicAdd(&h[d * TBINS + tb], 1);
        atomicAdd(&vs[d], (ull)(long long)llrintf(v * VSCALE));
    }
    __syncthreads();
    for (int j = tid; j < NKEY; j += CHUNK)
        g_chunkhist[blockIdx.x][j] = (unsigned short)h[j];
    if (tid < NDIM) g_chunkvsum[blockIdx.x][tid] = vs[tid];
}

// ---------------- P2: fused scan (1 block x 1024 thr; thread owns keys tid, tid+1024) --
__global__ void k_scan(int nchunks) {
    __shared__ int sA[1024], sB[1024];
    __shared__ ull vred[1024];
    const int tid = threadIdx.x;
    const int kA = tid, kB = tid + 1024;

    int runA = 0, runB = 0;
    for (int c = 0; c < nchunks; c++) {           // coalesced across threads
        int xA = g_chunkhist[c][kA];
        int xB = g_chunkhist[c][kB];
        g_chunkcum[c][kA] = (unsigned short)runA;
        g_chunkcum[c][kB] = (unsigned short)runB;
        runA += xA; runB += xB;
    }

    // per-dim v sums: thread (d = tid>>4, q = tid&15)
    {
        const int d = tid >> 4, q = tid & 15;
        ull acc = 0ULL;
        for (int c = q; c < nchunks; c += 16) acc += g_chunkvsum[c][d];
        vred[tid] = acc;
    }
    __syncthreads();
    if ((tid & 15) == 0) {
        ull a = 0ULL;
        for (int j = 0; j < 16; j++) a += vred[tid + j];
        g_sumv[tid >> 4] = (float)((long long)a) * VSCALE_INV;
    }

    // dual Hillis-Steele inclusive scans over 1024 key-totals each
    int incA = runA, incB = runB;
    sA[tid] = incA; sB[tid] = incB;
    __syncthreads();
    for (int ofs = 1; ofs < 1024; ofs <<= 1) {
        int aA = 0, aB = 0;
        if (tid >= ofs) { aA = sA[tid - ofs]; aB = sB[tid - ofs]; }
        __syncthreads();
        incA += aA; incB += aB;
        sA[tid] = incA; sB[tid] = incB;
        __syncthreads();
    }
    const int totalA = sA[1023];
    g_binoff[kA] = incA - runA;                   // exclusive prefix
    g_binoff[kB] = totalA + incB - runB;
    if (tid == 1023) g_binoff[NKEY] = totalA + incB;
}

// ---------------- P3: stable scatter, two-phase parallel rank (512 thr, 2 syncs) ----
__global__ void k_scatter(const float* __restrict__ S,
                          const float* __restrict__ alpha,
                          int n) {
    __shared__ unsigned char wcnt[16][NKEY];      // per-warp per-key counts (32KB)
    const int tid  = threadIdx.x;
    const int c    = blockIdx.x;
    const int lane = tid & 31;
    const int warp = tid >> 5;

    {
        unsigned int* w32 = (unsigned int*)&wcnt[0][0];
        for (int j = tid; j < (16 * NKEY) / 4; j += CHUNK) w32[j] = 0u;
    }

    int i = c * CHUNK + tid;
    int key = -1;
    float t = 0.f, v = 0.f;
    if (i < n) {
        t = S[i * 3 + 0];
        v = S[i * 3 + 1];
        int d = (int)S[i * 3 + 2];
        int tb = (int)(t * (float)TBINS);
        tb = max(0, min(TBINS - 1, tb));
        key = d * TBINS + tb;
    }
    __syncthreads();

    // intra-warp stable rank among equal keys
    unsigned m  = __match_any_sync(0xffffffffu, key);
    int rw      = __popc(m & ((1u << lane) - 1));
    int ldr     = __ffs(m) - 1;

    // phase 1: leaders publish per-warp counts
    if (key >= 0 && lane == ldr) wcnt[warp][key] = (unsigned char)__popc(m);
    __syncthreads();

    if (key >= 0) {
        // phase 2: base = counts of earlier warps for this key
        int grpbase = 0;
#pragma unroll
        for (int w = 0; w < 16; w++)
            if (w < warp) grpbase += (int)wcnt[w][key];

        int pos = g_binoff[key] + (int)g_chunkcum[c][key] + grpbase + rw;
        float tm = (t > 0.0f) ? t : 1.0e9f;     // masked -> exp underflows to 0
        float negC = -__ldg(alpha) * LOG2E;
        float B = -2.0f * negC * tm;            // arg = A + B*r + C = negC*(r-t)^2
        float Cc = negC * tm * tm;
        ulonglong2 bc;
        bc.x = pack2(B, B);
        bc.y = pack2(Cc, Cc);
        g_bc[pos] = bc;
        g_vv[pos] = pack2(v, v);
    }
}

// ---------------- main: 64-thr CTAs, 4 r's/thread, strided slabs, 3-segment loop ----
// grid = (R/256=8, NDIM, NSLAB=10) = 5120 CTAs x 64 thr -> refillable occupancy
#define KS_LOOP(LIMIT, DO_KC)                                           \
    _Pragma("unroll 2")                                                 \
    for (; i < (LIMIT); i += NSLAB) {                                   \
        ulonglong2 bc = __ldg(&g_bc[i]);                                \
        ull vp = __ldg(&g_vv[i]);                                       \
        ull g01 = fma2(bc.x, rr01, add2(bc.y, A01));                    \
        ull g23 = fma2(bc.x, rr23, add2(bc.y, A23));                    \
        float x0, x1, x2, x3;                                           \
        unpack2(g01, x0, x1); unpack2(g23, x2, x3);                     \
        ull e01 = pack2(ex2f(x0), ex2f(x1));                            \
        ull e23 = pack2(ex2f(x2), ex2f(x3));                            \
        ws01 = add2(ws01, e01); wsv01 = fma2(e01, vp, wsv01);           \
        ws23 = add2(ws23, e23); wsv23 = fma2(e23, vp, wsv23);           \
        if (DO_KC) {                                                    \
            ull t2 = mul2(e01, e01), t4 = mul2(t2, t2);                 \
            ull eA = mul2(mul2(t4, t4), t2);                            \
            ull u2 = mul2(e23, e23), u4 = mul2(u2, u2);                 \
            ull eB = mul2(mul2(u4, u4), u2);                            \
            wc01 = add2(wc01, eA); wcv01 = fma2(eA, vp, wcv01);         \
            wc23 = add2(wc23, eB); wcv23 = fma2(eB, vp, wcv23);         \
        }                                                               \
    }

__global__ void __launch_bounds__(64) k_main(const float* __restrict__ ref,
                                             const float* __restrict__ alpha,
                                             int R) {
    const int d   = blockIdx.y;
    const int z   = blockIdx.z;
    const int tid = threadIdx.x;
    const int rb  = blockIdx.x * 256;

    const int r0 = rb + tid, r1 = r0 + 64, r2 = r0 + 128, r3 = r0 + 192;
    const int idx0 = (r0 * NSLAB + z) * NDIM + d;
    const int idx1 = (r1 * NSLAB + z) * NDIM + d;
    const int idx2 = (r2 * NSLAB + z) * NDIM + d;
    const int idx3 = (r3 * NSLAB + z) * NDIM + d;

    const float rlo = __ldg(ref + rb);
    const float rhi = __ldg(ref + rb + 255);

    // Ks window bins
    int sb0 = max(0, (int)floorf((rlo - DWS) * (float)TBINS));
    int sb1 = min(TBINS, (int)floorf((rhi + DWS) * (float)TBINS) + 1);
    const int s0 = g_binoff[d * TBINS + sb0];
    const int s1 = g_binoff[d * TBINS + sb1];

    // Kc window bins (nested: c0 >= s0, c1 <= s1)
    int cb0 = max(0, (int)floorf((rlo - DWC) * (float)TBINS));
    int cb1 = min(TBINS, (int)floorf((rhi + DWC) * (float)TBINS) + 1);
    const int c0 = g_binoff[d * TBINS + cb0];
    const int c1 = g_binoff[d * TBINS + cb1];

    const float negC = -__ldg(alpha) * LOG2E;
    const float f0 = __ldg(ref + r0), f1 = __ldg(ref + r1);
    const float f2 = __ldg(ref + r2), f3 = __ldg(ref + r3);
    const ull rr01 = pack2(f0, f1);
    const ull rr23 = pack2(f2, f3);
    const ull A01  = pack2(negC * f0 * f0, negC * f1 * f1);
    const ull A23  = pack2(negC * f2 * f2, negC * f3 * f3);

    ull ws01 = 0, wsv01 = 0, ws23 = 0, wsv23 = 0;
    ull wc01 = 0, wcv01 = 0, wc23 = 0, wcv23 = 0;

    // strided over slab z: i = s0+z, s0+z+NSLAB, ... ; segments carry i forward
    int i = s0 + z;
    KS_LOOP(c0, false)    // [s0+z, c0): Ks only
    KS_LOOP(c1, true)     // [.., c1):   Ks + Kc
    KS_LOOP(s1, false)    // [.., s1):   Ks only

    float s0f, s1f, v0f, v1f, c0f, c1f, w0f, w1f;
    unpack2(ws01, s0f, s1f); unpack2(wsv01, v0f, v1f);
    unpack2(wc01, c0f, c1f); unpack2(wcv01, w0f, w1f);
    g_acc[idx0] = make_float4(s0f, v0f, c0f, w0f);
    g_acc[idx1] = make_float4(s1f, v1f, c1f, w1f);
    unpack2(ws23, s0f, s1f); unpack2(wsv23, v0f, v1f);
    unpack2(wc23, c0f, c1f); unpack2(wcv23, w0f, w1f);
    g_acc[idx2] = make_float4(s0f, v0f, c0f, w0f);
    g_acc[idx3] = make_float4(s1f, v1f, c1f, w1f);
}

// ---------------- finalize: 512 blocks x 256 thr, 4 r's per block, float4 loads -----
__global__ void __launch_bounds__(256) k_finalize(const float* __restrict__ rho,
                                                  float* __restrict__ out,
                                                  int R, float Rinv) {
    __shared__ float s_lam[4][NDIM + 1];
    __shared__ float s_ksv[4][NDIM + 1];
    __shared__ float s_coa[4][NDIM + 1];
    __shared__ float s_den[4];

    const int tid = threadIdx.x;
    const int r0  = blockIdx.x * 4;
    const int d   = tid & 63;
    const int rl  = tid >> 6;
    const int r   = r0 + rl;

    {
        const int cnt = g_binoff[(d + 1) * TBINS] - g_binoff[d * TBINS];
        const float ec = EPS * (float)(cnt + 1);
        const float ev = EPS * g_sumv[d];
        float lam_s = ec, ksv = ev, lam_c = ec, kcv = ev;
#pragma unroll
        for (int z = 0; z < NSLAB; z++) {
            float4 a = g_acc[(r * NSLAB + z) * NDIM + d];   // coalesced
            lam_s += a.x; ksv += a.y; lam_c += a.z; kcv += a.w;
        }
        s_lam[rl][d] = lam_s;
        s_ksv[rl][d] = ksv;
        s_coa[rl][d] = __fdividef(kcv, lam_c);
    }
    __syncthreads();

    {
        const int wid  = tid >> 5;
        const int lane = tid & 31;
        if (wid < 4) {
            float p = s_lam[wid][lane] + s_lam[wid][lane + 32];
            p += __shfl_xor_sync(0xffffffffu, p, 16);
            p += __shfl_xor_sync(0xffffffffu, p, 8);
            p += __shfl_xor_sync(0xffffffffu, p, 4);
            p += __shfl_xor_sync(0xffffffffu, p, 2);
            p += __shfl_xor_sync(0xffffffffu, p, 1);
            if (lane == 0) s_den[wid] = p;
        }
    }
    __syncthreads();

    float acc = 0.0f;
#pragma unroll
    for (int k = 0; k < NDIM; k++)
        acc = fmaf(s_ksv[rl][k], __ldg(&rho[k * NDIM + d]), acc);
    const float cr = __fdividef(acc, s_den[rl]);

    float* o = out + (long long)r * (3 * NDIM);
    o[d]            = s_lam[rl][d] * Rinv;   // lam
    o[NDIM + d]     = cr;                    // cross
    o[2 * NDIM + d] = s_coa[rl][d] - cr;     // transient
}

// ---------------- launch ----------------
extern "C" void kernel_launch(void* const* d_in, const int* in_sizes, int n_in,
                              void* d_out, int out_size) {
    const float* S     = (const float*)d_in[0];
    const float* ref   = (const float*)d_in[1];
    const float* alpha = (const float*)d_in[2];
    const float* rho   = (const float*)d_in[3];
    const int n = in_sizes[0] / 3;
    const int R = in_sizes[1];
    int nchunks = (n + CHUNK - 1) / CHUNK;
    if (nchunks > MAXCHUNKS) nchunks = MAXCHUNKS;

    k_hist<<<nchunks, CHUNK>>>(S, n);
    k_scan<<<1, 1024>>>(nchunks);
    k_scatter<<<nchunks, CHUNK>>>(S, alpha, n);

    dim3 gm(R / 256, NDIM, NSLAB);
    k_main<<<gm, 64>>>(ref, alpha, R);

    k_finalize<<<R / 4, 256>>>(rho, (float*)d_out, R, 1.0f / (float)R);
}